// round 13
// baseline (speedup 1.0000x reference)
#include <cuda_runtime.h>
#include <cuda_fp16.h>

#define Bc 2
#define Hc 12
#define Sc 2048
#define Dc 64
#define TQ 128
#define TK 64
#define NTH 128
#define STRD 72           // smem row stride in halves (64 + 8 pad, 144B)
#define SCALE 0.125f      // 1/sqrt(64)
#define NKT (Sc / TK)     // 32

// g_fmp (uint4): (((b*16+qt)*32+kt)*8 + w*2+mb)*128 + part*32 + lane
__device__ __align__(16) uint4 g_fmp[(size_t)Bc * 16 * 32 * 8 * 128];
// K/V B-fragments in consumer order: ((bh*32+kt)*16 + ks*4+ntp)*32 + lane
__device__ __align__(16) uint4 g_kf[(size_t)Bc * Hc * NKT * 16 * 32];
__device__ __align__(16) uint4 g_vf[(size_t)Bc * Hc * NKT * 16 * 32];
__device__ __align__(16) unsigned g_ps[(size_t)Bc * Hc * Sc * Sc / 2];  // 201 MB

__global__ void prep_fm_kernel(const float* __restrict__ freq,
                               const int*  __restrict__ mask) {
    unsigned idx = blockIdx.x * blockDim.x + threadIdx.x;   // one uint4 out
    int lane = idx & 31, part = (idx >> 5) & 3, mbw = (idx >> 7) & 7;
    int kt = (idx >> 10) & 31, qt = (idx >> 15) & 15, b = idx >> 19;
    int w = mbw >> 1, mb = mbw & 1;
    int g = lane >> 2, tg = lane & 3;
    int q = qt * TQ + w * 32 + mb * 16 + g + ((part >> 1) << 3);
    const float* fr = freq + ((size_t)b * Sc + q) * Sc;
    const int*   mr = mask + ((size_t)b * Sc + q) * Sc;
    int kbase = kt * 64 + (part & 1) * 32 + tg * 2;
    unsigned out[4];
    #pragma unroll
    for (int j = 0; j < 4; ++j) {
        int k = kbase + j * 8;
        float2 f = *(const float2*)(fr + k);
        int2   m = *(const int2*)(mr + k);
        __half2 h = __floats2half2_rn(m.x ? __logf(f.x) : -60000.0f,
                                      m.y ? __logf(f.y) : -60000.0f);
        out[j] = *(unsigned*)&h;
    }
    g_fmp[idx] = make_uint4(out[0], out[1], out[2], out[3]);
}

__device__ __forceinline__ void ldsm4(unsigned& r0, unsigned& r1, unsigned& r2,
                                      unsigned& r3, unsigned addr) {
    asm volatile("ldmatrix.sync.aligned.m8n8.x4.shared.b16 {%0,%1,%2,%3}, [%4];"
                 : "=r"(r0), "=r"(r1), "=r"(r2), "=r"(r3) : "r"(addr));
}

__device__ __forceinline__ void ldsm4t(unsigned& r0, unsigned& r1, unsigned& r2,
                                       unsigned& r3, unsigned addr) {
    asm volatile("ldmatrix.sync.aligned.m8n8.x4.trans.shared.b16 {%0,%1,%2,%3}, [%4];"
                 : "=r"(r0), "=r"(r1), "=r"(r2), "=r"(r3) : "r"(addr));
}

// one CTA per (b, h, kt): stage 64x64 K,V fp32->fp16 in smem, emit B-fragments
// by executing the consumer's exact ldsm4 / ldsm4t, then STG.128 in consumer order.
__global__ void __launch_bounds__(NTH)
prep_kvfrag_kernel(const float* __restrict__ K, const float* __restrict__ V) {
    __shared__ __align__(16) __half Kt[TK * STRD];
    __shared__ __align__(16) __half Vt[TK * STRD];
    const int tid = threadIdx.x;
    const int w = tid >> 5, lane = tid & 31;
    const int kt = blockIdx.x, h = blockIdx.y, b = blockIdx.z;
    const size_t bh = (size_t)b * Hc + h;
    const float* Kg = K + (bh * Sc + (size_t)kt * TK) * Dc;
    const float* Vg = V + (bh * Sc + (size_t)kt * TK) * Dc;

    #pragma unroll
    for (int i = tid; i < TK * 16; i += NTH) {
        int r = i >> 4, c = (i & 15) * 4;
        float4 vk = *(const float4*)(Kg + (size_t)r * Dc + c);
        float4 vv = *(const float4*)(Vg + (size_t)r * Dc + c);
        __half2 k0 = __floats2half2_rn(vk.x, vk.y), k1 = __floats2half2_rn(vk.z, vk.w);
        __half2 v0 = __floats2half2_rn(vv.x, vv.y), v1 = __floats2half2_rn(vv.z, vv.w);
        uint2 uk; uk.x = *(unsigned*)&k0; uk.y = *(unsigned*)&k1;
        uint2 uv; uv.x = *(unsigned*)&v0; uv.y = *(unsigned*)&v1;
        *(uint2*)(Kt + r * STRD + c) = uk;
        *(uint2*)(Vt + r * STRD + c) = uv;
    }
    __syncthreads();

    const unsigned kt_u = (unsigned)__cvta_generic_to_shared(Kt);
    const unsigned vt_u = (unsigned)__cvta_generic_to_shared(Vt);
    const int brow = ((lane >> 4) & 1) * 8 + (lane & 7);
    const int bcol = ((lane >> 3) & 1) * 8;
    const unsigned addrB = kt_u + ((brow * STRD + bcol) << 1);
    const int vrow = ((lane >> 3) & 1) * 8 + (lane & 7);
    const int vcol = ((lane >> 4) & 1) * 8;
    const unsigned addrV = vt_u + ((vrow * STRD + vcol) << 1);

    uint4* kout = g_kf + ((bh * NKT + kt) * 16) * 32 + lane;
    uint4* vout = g_vf + ((bh * NKT + kt) * 16) * 32 + lane;
    #pragma unroll
    for (int j = 0; j < 4; ++j) {
        int p = w * 4 + j;                 // p = ks*4 + ntp
        int ks = p >> 2, ntp = p & 3;
        unsigned r0, r1, r2, r3;
        ldsm4(r0, r1, r2, r3, addrB + (ntp * 16 * STRD + ks * 16) * 2);
        kout[p * 32] = make_uint4(r0, r1, r2, r3);
        ldsm4t(r0, r1, r2, r3, addrV + (ks * 16 * STRD + ntp * 16) * 2);
        vout[p * 32] = make_uint4(r0, r1, r2, r3);
    }
}

__device__ __forceinline__ void mma_f16(float* c, const unsigned* a, const unsigned* b) {
    asm volatile(
        "mma.sync.aligned.m16n8k16.row.col.f32.f16.f16.f32 "
        "{%0,%1,%2,%3}, {%4,%5,%6,%7}, {%8,%9}, {%0,%1,%2,%3};\n"
        : "+f"(c[0]), "+f"(c[1]), "+f"(c[2]), "+f"(c[3])
        : "r"(a[0]), "r"(a[1]), "r"(a[2]), "r"(a[3]), "r"(b[0]), "r"(b[1]));
}

__global__ void __launch_bounds__(NTH)
attn_kernel(const float* __restrict__ Q, float* __restrict__ Out,
            float* __restrict__ Pout, int writep) {
    __shared__ __align__(16) __half smem_buf[TQ * STRD];   // Q prologue only

    const int tid = threadIdx.x;
    const int w = tid >> 5, lane = tid & 31;
    const int g = lane >> 2, tg = lane & 3;
    const int wq = w * 32;
    const int h = blockIdx.x, qt = blockIdx.y, b = blockIdx.z;
    const int q0 = qt * TQ;

    const size_t bh = (size_t)b * Hc + h;
    const float* Qg = Q + (bh * Sc + q0) * Dc;
    float* Og = Out + (bh * Sc + q0) * Dc;
    float* Pg = Pout + (bh * Sc + q0) * Sc;

    // scratch exp fragments (proven layout)
    uint4* scr = (uint4*)g_ps +
                 ((((bh * (Sc / TQ) + qt) * NKT) * 4 + w) * 2) * 128 + lane;
    // FM fragments (h-independent)
    const uint4* fmb = g_fmp +
                 ((((size_t)b * 16 + qt) * NKT) * 8 + w * 2) * 128 + lane;
    // K/V fragments (warp-invariant, qt-invariant -> L2 hot)
    const uint4* kfb = g_kf + (bh * NKT * 16) * 32 + lane;
    const uint4* vfb = g_vf + (bh * NKT * 16) * 32 + lane;

    const unsigned smem_u = (unsigned)__cvta_generic_to_shared(smem_buf);

    // ---- Q prologue: stage fp32->fp16, load A-fragments, then smem is dead ----
    #pragma unroll
    for (int i = tid; i < TQ * 16; i += NTH) {
        int r = i >> 4, c = (i & 15) * 4;
        float4 v = *(const float4*)(Qg + (size_t)r * Dc + c);
        __half2 p0 = __floats2half2_rn(v.x, v.y), p1 = __floats2half2_rn(v.z, v.w);
        uint2 u; u.x = *(unsigned*)&p0; u.y = *(unsigned*)&p1;
        *(uint2*)(smem_buf + r * STRD + c) = u;
    }
    __syncthreads();
    unsigned qa[2][4][4];
    #pragma unroll
    for (int mb = 0; mb < 2; ++mb) {
        unsigned addrA = smem_u +
            (((wq + 16 * mb + (lane & 15)) * STRD + (lane >> 4) * 8) << 1);
        #pragma unroll
        for (int ks = 0; ks < 4; ++ks)
            ldsm4(qa[mb][ks][0], qa[mb][ks][1], qa[mb][ks][2], qa[mb][ks][3],
                  addrA + ks * 32);
    }

    // ---------------- pass 1 (no barriers): scores -> exp frags + Z ----------
    float z[2][2] = {{0.0f, 0.0f}, {0.0f, 0.0f}};
    for (int kt = 0; kt < NKT; ++kt) {
        uint4 fm[2][4];
        #pragma unroll
        for (int mb = 0; mb < 2; ++mb) {
            const uint4* fp = fmb + ((size_t)kt * 8 + mb) * 128;
            fm[mb][0] = fp[0];  fm[mb][1] = fp[32];
            fm[mb][2] = fp[64]; fm[mb][3] = fp[96];
        }
        const uint4* kfp = kfb + (size_t)kt * 16 * 32;

        float sacc[2][8][4];
        #pragma unroll
        for (int mb = 0; mb < 2; ++mb)
            #pragma unroll
            for (int nt = 0; nt < 8; ++nt)
                sacc[mb][nt][0] = sacc[mb][nt][1] = sacc[mb][nt][2] = sacc[mb][nt][3] = 0.0f;

        #pragma unroll
        for (int ks = 0; ks < 4; ++ks) {
            #pragma unroll
            for (int ntp = 0; ntp < 4; ++ntp) {
                uint4 bf4 = kfp[(ks * 4 + ntp) * 32];
                unsigned blo[2] = {bf4.x, bf4.y}, bhi[2] = {bf4.z, bf4.w};
                #pragma unroll
                for (int mb = 0; mb < 2; ++mb) {
                    mma_f16(sacc[mb][2 * ntp],     qa[mb][ks], blo);
                    mma_f16(sacc[mb][2 * ntp + 1], qa[mb][ks], bhi);
                }
            }
        }

        #pragma unroll
        for (int mb = 0; mb < 2; ++mb) {
            unsigned sl[8], sh[8];
            #pragma unroll
            for (int nt = 0; nt < 8; ++nt) {
                unsigned flo_u = ((const unsigned*)&fm[mb][nt >> 2])[nt & 3];
                unsigned fhi_u = ((const unsigned*)&fm[mb][2 + (nt >> 2)])[nt & 3];
                float2 flo = __half22float2(*(__half2*)&flo_u);
                float2 fhi = __half22float2(*(__half2*)&fhi_u);
                float p0 = __expf(fmaf(sacc[mb][nt][0], SCALE, flo.x));
                float p1 = __expf(fmaf(sacc[mb][nt][1], SCALE, flo.y));
                float p2 = __expf(fmaf(sacc[mb][nt][2], SCALE, fhi.x));
                float p3 = __expf(fmaf(sacc[mb][nt][3], SCALE, fhi.y));
                z[mb][0] += p0 + p1;
                z[mb][1] += p2 + p3;
                __half2 hlo = __floats2half2_rn(p0, p1);
                __half2 hhi = __floats2half2_rn(p2, p3);
                sl[nt] = *(unsigned*)&hlo;
                sh[nt] = *(unsigned*)&hhi;
            }
            uint4* sp = scr + ((size_t)kt * 8 + mb) * 128;
            sp[0]  = make_uint4(sl[0], sl[1], sl[2], sl[3]);
            sp[32] = make_uint4(sl[4], sl[5], sl[6], sl[7]);
            sp[64] = make_uint4(sh[0], sh[1], sh[2], sh[3]);
            sp[96] = make_uint4(sh[4], sh[5], sh[6], sh[7]);
        }
    }
    float iz[2][2];
    #pragma unroll
    for (int mb = 0; mb < 2; ++mb)
        #pragma unroll
        for (int hf = 0; hf < 2; ++hf) {
            float zz = z[mb][hf];
            zz += __shfl_xor_sync(0xffffffffu, zz, 1);
            zz += __shfl_xor_sync(0xffffffffu, zz, 2);
            iz[mb][hf] = 1.0f / zz;
        }

    // ---------------- pass 2 (no barriers): normalize P + PV ----------------
    float oacc[2][8][4];
    #pragma unroll
    for (int mb = 0; mb < 2; ++mb)
        #pragma unroll
        for (int nt = 0; nt < 8; ++nt)
            oacc[mb][nt][0] = oacc[mb][nt][1] = oacc[mb][nt][2] = oacc[mb][nt][3] = 0.0f;

    float2* Pp[2][2];
    #pragma unroll
    for (int mb = 0; mb < 2; ++mb) {
        Pp[mb][0] = (float2*)(Pg + (size_t)(wq + 16 * mb + g) * Sc) + tg;
        Pp[mb][1] = (float2*)(Pg + (size_t)(wq + 16 * mb + g + 8) * Sc) + tg;
    }

    for (int kt = 0; kt < NKT; ++kt) {
        unsigned sl[2][8], sh[2][8];
        #pragma unroll
        for (int mb = 0; mb < 2; ++mb) {
            uint4* sp = scr + ((size_t)kt * 8 + mb) * 128;
            uint4 a0 = sp[0], a1 = sp[32], a2 = sp[64], a3 = sp[96];
            sl[mb][0] = a0.x; sl[mb][1] = a0.y; sl[mb][2] = a0.z; sl[mb][3] = a0.w;
            sl[mb][4] = a1.x; sl[mb][5] = a1.y; sl[mb][6] = a1.z; sl[mb][7] = a1.w;
            sh[mb][0] = a2.x; sh[mb][1] = a2.y; sh[mb][2] = a2.z; sh[mb][3] = a2.w;
            sh[mb][4] = a3.x; sh[mb][5] = a3.y; sh[mb][6] = a3.z; sh[mb][7] = a3.w;
        }
        const uint4* vfp = vfb + (size_t)kt * 16 * 32;

        if (writep) {
            #pragma unroll
            for (int mb = 0; mb < 2; ++mb)
                #pragma unroll
                for (int nt = 0; nt < 8; ++nt) {
                    float2 plo = __half22float2(*(__half2*)&sl[mb][nt]);
                    float2 phi = __half22float2(*(__half2*)&sh[mb][nt]);
                    __stwt(Pp[mb][0] + kt * 32 + nt * 4,
                           make_float2(plo.x * iz[mb][0], plo.y * iz[mb][0]));
                    __stwt(Pp[mb][1] + kt * 32 + nt * 4,
                           make_float2(phi.x * iz[mb][1], phi.y * iz[mb][1]));
                }
        }

        #pragma unroll
        for (int ks2 = 0; ks2 < 4; ++ks2) {
            #pragma unroll
            for (int ntp = 0; ntp < 4; ++ntp) {
                uint4 v4 = vfp[(ks2 * 4 + ntp) * 32];
                unsigned blo[2] = {v4.x, v4.y}, bhi[2] = {v4.z, v4.w};
                #pragma unroll
                for (int mb = 0; mb < 2; ++mb) {
                    unsigned a[4] = {sl[mb][2 * ks2], sh[mb][2 * ks2],
                                     sl[mb][2 * ks2 + 1], sh[mb][2 * ks2 + 1]};
                    mma_f16(oacc[mb][2 * ntp],     a, blo);
                    mma_f16(oacc[mb][2 * ntp + 1], a, bhi);
                }
            }
        }
    }

    // scale by 1/Z and write O tile
    #pragma unroll
    for (int mb = 0; mb < 2; ++mb) {
        float* o0 = Og + (size_t)(wq + 16 * mb + g) * Dc;
        float* o1 = Og + (size_t)(wq + 16 * mb + g + 8) * Dc;
        #pragma unroll
        for (int nt = 0; nt < 8; ++nt) {
            int col = nt * 8 + 2 * tg;
            *(float2*)(o0 + col) = make_float2(oacc[mb][nt][0] * iz[mb][0],
                                               oacc[mb][nt][1] * iz[mb][0]);
            *(float2*)(o1 + col) = make_float2(oacc[mb][nt][2] * iz[mb][1],
                                               oacc[mb][nt][3] * iz[mb][1]);
        }
    }
}

extern "C" void kernel_launch(void* const* d_in, const int* in_sizes, int n_in,
                              void* d_out, int out_size) {
    const float* Q    = (const float*)d_in[0];
    const float* K    = (const float*)d_in[1];
    const float* V    = (const float*)d_in[2];
    const float* freq = (const float*)d_in[3];
    const int*   mask = (const int*)d_in[4];

    const size_t out_elems = (size_t)Bc * Hc * Sc * Dc;   // 3,145,728
    float* Out  = (float*)d_out;
    float* Pout = (float*)d_out + out_elems;              // p_attn follows out
    int writep  = (out_size > (int)out_elems) ? 1 : 0;

    {
        int total = Bc * 16 * 32 * 8 * 128;               // one thread per uint4
        prep_fm_kernel<<<total / 256, 256>>>(freq, mask);
    }
    {
        dim3 grid(NKT, Hc, Bc);                           // one CTA per K/V tile
        prep_kvfrag_kernel<<<grid, NTH>>>(K, V);
    }
    {
        dim3 grid(Hc, Sc / TQ, Bc);
        attn_kernel<<<grid, NTH>>>(Q, Out, Pout, writep);
    }
}